// round 11
// baseline (speedup 1.0000x reference)
#include <cuda_runtime.h>
#include <cuda_fp16.h>
#include <cstdint>

#define M_NODES 50000
#define K_FEAT  256
#define N_HID   128
#define NUM_EDGES 1600000
#define SCAN_NB  ((M_NODES + 255) / 256)   // 196

// ---------------------------------------------------------------------------
// Device scratch (static; no runtime allocation)
// ---------------------------------------------------------------------------
__device__ __half g_support[M_NODES * N_HID];  // 12.8 MB (fp16)
__device__ int   g_deg[M_NODES];
__device__ int   g_start[M_NODES];
__device__ int   g_cursor[M_NODES];
__device__ int   g_bsum[SCAN_NB];
__device__ int2  g_edge[NUM_EDGES];            // (src, bitcast(w))

// ---------------------------------------------------------------------------
// Kernel A: support = x @ W  via tf32 mma.sync (m16n8k8); fp16 epilogue
// ---------------------------------------------------------------------------
#define A_STRIDE 36
#define B_STRIDE 136

__device__ __forceinline__ uint32_t f32_to_tf32(float f) {
    uint32_t r;
    asm("cvt.rna.tf32.f32 %0, %1;" : "=r"(r) : "f"(f));
    return r;
}

__global__ __launch_bounds__(256) void gemm_tf32_kernel(
    const float* __restrict__ A,
    const float* __restrict__ B,
    __half* __restrict__ C)
{
    __shared__ uint32_t As[128 * A_STRIDE];
    __shared__ uint32_t Bs[32 * B_STRIDE];

    const int tid  = threadIdx.x;
    const int warp = tid >> 5;
    const int lane = tid & 31;
    const int warpM = warp >> 1;
    const int warpN = warp & 1;
    const int rbase = warpM * 32;
    const int nbase = warpN * 64;
    const int m0 = blockIdx.x * 128;

    const int qrow = lane >> 2;
    const int qcol = lane & 3;

    float acc[2][8][4];
    #pragma unroll
    for (int mt = 0; mt < 2; mt++)
        #pragma unroll
        for (int nt = 0; nt < 8; nt++)
            #pragma unroll
            for (int i = 0; i < 4; i++)
                acc[mt][nt][i] = 0.f;

    for (int k0g = 0; k0g < K_FEAT; k0g += 32) {
        #pragma unroll
        for (int i = 0; i < 4; i++) {
            int f = tid + i * 256;
            int row = f >> 3;
            int c4  = (f & 7) * 4;
            float4 v = make_float4(0.f, 0.f, 0.f, 0.f);
            int gm = m0 + row;
            if (gm < M_NODES)
                v = *(const float4*)(A + (size_t)gm * K_FEAT + k0g + c4);
            uint32_t* p = &As[row * A_STRIDE + c4];
            p[0] = f32_to_tf32(v.x);
            p[1] = f32_to_tf32(v.y);
            p[2] = f32_to_tf32(v.z);
            p[3] = f32_to_tf32(v.w);
        }
        #pragma unroll
        for (int i = 0; i < 4; i++) {
            int f = tid + i * 256;
            int row = f >> 5;
            int c4  = (f & 31) * 4;
            float4 v = *(const float4*)(B + (size_t)(k0g + row) * N_HID + c4);
            uint32_t* p = &Bs[row * B_STRIDE + c4];
            p[0] = f32_to_tf32(v.x);
            p[1] = f32_to_tf32(v.y);
            p[2] = f32_to_tf32(v.z);
            p[3] = f32_to_tf32(v.w);
        }
        __syncthreads();

        #pragma unroll
        for (int ks = 0; ks < 4; ks++) {
            const int k0 = ks * 8;
            uint32_t a[2][4];
            #pragma unroll
            for (int mt = 0; mt < 2; mt++) {
                int r = rbase + mt * 16 + qrow;
                a[mt][0] = As[(r    ) * A_STRIDE + k0 + qcol    ];
                a[mt][1] = As[(r + 8) * A_STRIDE + k0 + qcol    ];
                a[mt][2] = As[(r    ) * A_STRIDE + k0 + qcol + 4];
                a[mt][3] = As[(r + 8) * A_STRIDE + k0 + qcol + 4];
            }
            uint32_t b[8][2];
            #pragma unroll
            for (int nt = 0; nt < 8; nt++) {
                int c = nbase + nt * 8 + qrow;
                b[nt][0] = Bs[(k0 + qcol    ) * B_STRIDE + c];
                b[nt][1] = Bs[(k0 + qcol + 4) * B_STRIDE + c];
            }
            #pragma unroll
            for (int mt = 0; mt < 2; mt++)
                #pragma unroll
                for (int nt = 0; nt < 8; nt++)
                    asm volatile(
                        "mma.sync.aligned.m16n8k8.row.col.f32.tf32.tf32.f32 "
                        "{%0,%1,%2,%3}, {%4,%5,%6,%7}, {%8,%9}, {%0,%1,%2,%3};"
                        : "+f"(acc[mt][nt][0]), "+f"(acc[mt][nt][1]),
                          "+f"(acc[mt][nt][2]), "+f"(acc[mt][nt][3])
                        : "r"(a[mt][0]), "r"(a[mt][1]), "r"(a[mt][2]), "r"(a[mt][3]),
                          "r"(b[nt][0]), "r"(b[nt][1]));
        }
        __syncthreads();
    }

    #pragma unroll
    for (int mt = 0; mt < 2; mt++) {
        int row0 = m0 + rbase + mt * 16 + qrow;
        #pragma unroll
        for (int nt = 0; nt < 8; nt++) {
            int col = nbase + nt * 8 + 2 * qcol;
            if (row0 < M_NODES)
                *(__half2*)(C + (size_t)row0 * N_HID + col) =
                    __floats2half2_rn(acc[mt][nt][0], acc[mt][nt][1]);
            if (row0 + 8 < M_NODES)
                *(__half2*)(C + (size_t)(row0 + 8) * N_HID + col) =
                    __floats2half2_rn(acc[mt][nt][2], acc[mt][nt][3]);
        }
    }
}

// ---------------------------------------------------------------------------
// Binning kernels. count/permute: 4 edges per thread for atomic-latency ILP.
// NUM_EDGES % 4 == 0.
// ---------------------------------------------------------------------------
__global__ __launch_bounds__(256) void count_kernel(
    const int* __restrict__ edge_index)
{
    int q = blockIdx.x * blockDim.x + threadIdx.x;   // quad index
    int e = q * 4;
    if (e >= NUM_EDGES) return;
    int4 d = *(const int4*)(edge_index + NUM_EDGES + e);
    atomicAdd(&g_deg[d.x], 1);
    atomicAdd(&g_deg[d.y], 1);
    atomicAdd(&g_deg[d.z], 1);
    atomicAdd(&g_deg[d.w], 1);
}

__global__ __launch_bounds__(256) void scan1_kernel()
{
    __shared__ int sh[256];
    int i = blockIdx.x * 256 + threadIdx.x;
    int v = (i < M_NODES) ? g_deg[i] : 0;
    sh[threadIdx.x] = v;
    __syncthreads();
    #pragma unroll
    for (int off = 1; off < 256; off <<= 1) {
        int t = (threadIdx.x >= off) ? sh[threadIdx.x - off] : 0;
        __syncthreads();
        sh[threadIdx.x] += t;
        __syncthreads();
    }
    if (i < M_NODES) g_start[i] = sh[threadIdx.x] - v;
    if (threadIdx.x == 255) g_bsum[blockIdx.x] = sh[255];
}

__global__ __launch_bounds__(256) void scan2_kernel()
{
    __shared__ int sh[256];
    int v = (threadIdx.x < SCAN_NB) ? g_bsum[threadIdx.x] : 0;
    sh[threadIdx.x] = v;
    __syncthreads();
    #pragma unroll
    for (int off = 1; off < 256; off <<= 1) {
        int t = (threadIdx.x >= off) ? sh[threadIdx.x - off] : 0;
        __syncthreads();
        sh[threadIdx.x] += t;
        __syncthreads();
    }
    if (threadIdx.x < SCAN_NB) g_bsum[threadIdx.x] = sh[threadIdx.x] - v;
}

__global__ __launch_bounds__(256) void scan3_kernel()
{
    int i = blockIdx.x * 256 + threadIdx.x;
    if (i >= M_NODES) return;
    int s = g_start[i] + g_bsum[blockIdx.x];
    g_start[i]  = s;
    g_cursor[i] = s;
}

__global__ __launch_bounds__(256) void permute_kernel(
    const int* __restrict__ edge_index,
    const float* __restrict__ edge_weight)
{
    int q = blockIdx.x * blockDim.x + threadIdx.x;
    int e = q * 4;
    if (e >= NUM_EDGES) return;

    int4   s = *(const int4*)  (edge_index + e);
    int4   d = *(const int4*)  (edge_index + NUM_EDGES + e);
    float4 w = *(const float4*)(edge_weight + e);

    // 4 independent atomics issued back-to-back (latency pipelined)
    int p0 = atomicAdd(&g_cursor[d.x], 1);
    int p1 = atomicAdd(&g_cursor[d.y], 1);
    int p2 = atomicAdd(&g_cursor[d.z], 1);
    int p3 = atomicAdd(&g_cursor[d.w], 1);

    g_edge[p0] = make_int2(s.x, __float_as_int(w.x));
    g_edge[p1] = make_int2(s.y, __float_as_int(w.y));
    g_edge[p2] = make_int2(s.z, __float_as_int(w.z));
    g_edge[p3] = make_int2(s.w, __float_as_int(w.w));
}

// ---------------------------------------------------------------------------
// Aggregate + bias + relu + log_softmax, fused. One warp per dst row.
// ---------------------------------------------------------------------------
__global__ __launch_bounds__(256) void aggregate_kernel(
    const __half* __restrict__ support,
    const float* __restrict__ bias,
    float* __restrict__ out)
{
    int row  = blockIdx.x * 8 + (threadIdx.x >> 5);
    int lane = threadIdx.x & 31;
    if (row >= M_NODES) return;

    int start = g_start[row];
    int deg   = g_deg[row];
    int end   = start + deg;

    float4 acc = make_float4(0.f, 0.f, 0.f, 0.f);

    for (int base = start; base < end; base += 32) {
        int n = end - base;
        if (n > 32) n = 32;
        int   s = 0;
        float w = 0.f;
        if (lane < n) {
            int2 r = __ldg(g_edge + base + lane);
            s = r.x;
            w = __int_as_float(r.y);
        }
        for (int k = 0; k < n; k++) {
            int   sk = __shfl_sync(0xFFFFFFFF, s, k);
            float wk = __shfl_sync(0xFFFFFFFF, w, k);
            uint2 raw = __ldg((const uint2*)(support + (size_t)sk * N_HID) + lane);
            __half2 h0 = *(__half2*)&raw.x;
            __half2 h1 = *(__half2*)&raw.y;
            float2 f0 = __half22float2(h0);
            float2 f1 = __half22float2(h1);
            acc.x = fmaf(f0.x, wk, acc.x);
            acc.y = fmaf(f0.y, wk, acc.y);
            acc.z = fmaf(f1.x, wk, acc.z);
            acc.w = fmaf(f1.y, wk, acc.w);
        }
    }

    float4 b = *(const float4*)(bias + lane * 4);
    acc.x = fmaxf(acc.x + b.x, 0.f);
    acc.y = fmaxf(acc.y + b.y, 0.f);
    acc.z = fmaxf(acc.z + b.z, 0.f);
    acc.w = fmaxf(acc.w + b.w, 0.f);

    float m = fmaxf(fmaxf(acc.x, acc.y), fmaxf(acc.z, acc.w));
    #pragma unroll
    for (int off = 16; off > 0; off >>= 1)
        m = fmaxf(m, __shfl_xor_sync(0xFFFFFFFF, m, off));

    float ssum = __expf(acc.x - m) + __expf(acc.y - m) +
                 __expf(acc.z - m) + __expf(acc.w - m);
    #pragma unroll
    for (int off = 16; off > 0; off >>= 1)
        ssum += __shfl_xor_sync(0xFFFFFFFF, ssum, off);

    float lse = m + __logf(ssum);
    float4 r = make_float4(acc.x - lse, acc.y - lse, acc.z - lse, acc.w - lse);
    *(float4*)(out + (size_t)row * N_HID + lane * 4) = r;
}

// ---------------------------------------------------------------------------
// Launch: GEMM on capture stream overlapped with binning on a forked stream.
// ---------------------------------------------------------------------------
extern "C" void kernel_launch(void* const* d_in, const int* in_sizes, int n_in,
                              void* d_out, int out_size)
{
    const float* x      = (const float*)d_in[0];
    const float* weight = (const float*)d_in[1];
    const float* bias   = (const float*)d_in[2];
    const int*   eidx   = (const int*)  d_in[3];
    const float* ew     = (const float*)d_in[4];
    float* out = (float*)d_out;

    __half* support;
    cudaGetSymbolAddress((void**)&support, g_support);
    void* degp;
    cudaGetSymbolAddress(&degp, g_deg);

    const int EQB = (NUM_EDGES / 4 + 255) / 256;   // quad-per-thread blocks

    cudaStream_t s2 = 0;
    bool dual = (cudaStreamCreateWithFlags(&s2, cudaStreamNonBlocking) == cudaSuccess);

    if (dual) {
        cudaEvent_t evFork, evJoin;
        cudaEventCreateWithFlags(&evFork, cudaEventDisableTiming);
        cudaEventCreateWithFlags(&evJoin, cudaEventDisableTiming);

        cudaEventRecord(evFork, 0);
        cudaStreamWaitEvent(s2, evFork, 0);

        cudaMemsetAsync(degp, 0, M_NODES * sizeof(int), s2);
        count_kernel<<<EQB, 256, 0, s2>>>(eidx);
        scan1_kernel<<<SCAN_NB, 256, 0, s2>>>();
        scan2_kernel<<<1, 256, 0, s2>>>();
        scan3_kernel<<<SCAN_NB, 256, 0, s2>>>();
        permute_kernel<<<EQB, 256, 0, s2>>>(eidx, ew);
        cudaEventRecord(evJoin, s2);

        gemm_tf32_kernel<<<(M_NODES + 127) / 128, 256>>>(x, weight, support);

        cudaStreamWaitEvent(0, evJoin, 0);
        aggregate_kernel<<<(M_NODES + 7) / 8, 256>>>(support, bias, out);
    } else {
        gemm_tf32_kernel<<<(M_NODES + 127) / 128, 256>>>(x, weight, support);
        cudaMemsetAsync(degp, 0, M_NODES * sizeof(int));
        count_kernel<<<EQB, 256>>>(eidx);
        scan1_kernel<<<SCAN_NB, 256>>>();
        scan2_kernel<<<1, 256>>>();
        scan3_kernel<<<SCAN_NB, 256>>>();
        permute_kernel<<<EQB, 256>>>(eidx, ew);
        aggregate_kernel<<<(M_NODES + 7) / 8, 256>>>(support, bias, out);
    }
}

// round 12
// speedup vs baseline: 1.0188x; 1.0188x over previous
#include <cuda_runtime.h>
#include <cuda_fp16.h>
#include <cstdint>

#define M_NODES 50000
#define K_FEAT  256
#define N_HID   128
#define NUM_EDGES 1600000
#define SCAN_NB  ((M_NODES + 255) / 256)   // 196

// ---------------------------------------------------------------------------
// Device scratch (static; no runtime allocation)
// ---------------------------------------------------------------------------
__device__ __half g_support[M_NODES * N_HID];  // 12.8 MB (fp16)
__device__ int   g_deg[M_NODES];
__device__ int   g_start[M_NODES];
__device__ int   g_cursor[M_NODES];
__device__ int   g_bsum[SCAN_NB];
__device__ int2  g_edge[NUM_EDGES];            // (src, bitcast(w))

// ---------------------------------------------------------------------------
// Kernel A: support = x @ W  via tf32 mma.sync (m16n8k8); fp16 epilogue
// ---------------------------------------------------------------------------
#define A_STRIDE 36
#define B_STRIDE 136

__device__ __forceinline__ uint32_t f32_to_tf32(float f) {
    uint32_t r;
    asm("cvt.rna.tf32.f32 %0, %1;" : "=r"(r) : "f"(f));
    return r;
}

__global__ __launch_bounds__(256) void gemm_tf32_kernel(
    const float* __restrict__ A,
    const float* __restrict__ B,
    __half* __restrict__ C)
{
    __shared__ uint32_t As[128 * A_STRIDE];
    __shared__ uint32_t Bs[32 * B_STRIDE];

    const int tid  = threadIdx.x;
    const int warp = tid >> 5;
    const int lane = tid & 31;
    const int warpM = warp >> 1;
    const int warpN = warp & 1;
    const int rbase = warpM * 32;
    const int nbase = warpN * 64;
    const int m0 = blockIdx.x * 128;

    const int qrow = lane >> 2;
    const int qcol = lane & 3;

    float acc[2][8][4];
    #pragma unroll
    for (int mt = 0; mt < 2; mt++)
        #pragma unroll
        for (int nt = 0; nt < 8; nt++)
            #pragma unroll
            for (int i = 0; i < 4; i++)
                acc[mt][nt][i] = 0.f;

    for (int k0g = 0; k0g < K_FEAT; k0g += 32) {
        #pragma unroll
        for (int i = 0; i < 4; i++) {
            int f = tid + i * 256;
            int row = f >> 3;
            int c4  = (f & 7) * 4;
            float4 v = make_float4(0.f, 0.f, 0.f, 0.f);
            int gm = m0 + row;
            if (gm < M_NODES)
                v = *(const float4*)(A + (size_t)gm * K_FEAT + k0g + c4);
            uint32_t* p = &As[row * A_STRIDE + c4];
            p[0] = f32_to_tf32(v.x);
            p[1] = f32_to_tf32(v.y);
            p[2] = f32_to_tf32(v.z);
            p[3] = f32_to_tf32(v.w);
        }
        #pragma unroll
        for (int i = 0; i < 4; i++) {
            int f = tid + i * 256;
            int row = f >> 5;
            int c4  = (f & 31) * 4;
            float4 v = *(const float4*)(B + (size_t)(k0g + row) * N_HID + c4);
            uint32_t* p = &Bs[row * B_STRIDE + c4];
            p[0] = f32_to_tf32(v.x);
            p[1] = f32_to_tf32(v.y);
            p[2] = f32_to_tf32(v.z);
            p[3] = f32_to_tf32(v.w);
        }
        __syncthreads();

        #pragma unroll
        for (int ks = 0; ks < 4; ks++) {
            const int k0 = ks * 8;
            uint32_t a[2][4];
            #pragma unroll
            for (int mt = 0; mt < 2; mt++) {
                int r = rbase + mt * 16 + qrow;
                a[mt][0] = As[(r    ) * A_STRIDE + k0 + qcol    ];
                a[mt][1] = As[(r + 8) * A_STRIDE + k0 + qcol    ];
                a[mt][2] = As[(r    ) * A_STRIDE + k0 + qcol + 4];
                a[mt][3] = As[(r + 8) * A_STRIDE + k0 + qcol + 4];
            }
            uint32_t b[8][2];
            #pragma unroll
            for (int nt = 0; nt < 8; nt++) {
                int c = nbase + nt * 8 + qrow;
                b[nt][0] = Bs[(k0 + qcol    ) * B_STRIDE + c];
                b[nt][1] = Bs[(k0 + qcol + 4) * B_STRIDE + c];
            }
            #pragma unroll
            for (int mt = 0; mt < 2; mt++)
                #pragma unroll
                for (int nt = 0; nt < 8; nt++)
                    asm volatile(
                        "mma.sync.aligned.m16n8k8.row.col.f32.tf32.tf32.f32 "
                        "{%0,%1,%2,%3}, {%4,%5,%6,%7}, {%8,%9}, {%0,%1,%2,%3};"
                        : "+f"(acc[mt][nt][0]), "+f"(acc[mt][nt][1]),
                          "+f"(acc[mt][nt][2]), "+f"(acc[mt][nt][3])
                        : "r"(a[mt][0]), "r"(a[mt][1]), "r"(a[mt][2]), "r"(a[mt][3]),
                          "r"(b[nt][0]), "r"(b[nt][1]));
        }
        __syncthreads();
    }

    #pragma unroll
    for (int mt = 0; mt < 2; mt++) {
        int row0 = m0 + rbase + mt * 16 + qrow;
        #pragma unroll
        for (int nt = 0; nt < 8; nt++) {
            int col = nbase + nt * 8 + 2 * qcol;
            if (row0 < M_NODES)
                *(__half2*)(C + (size_t)row0 * N_HID + col) =
                    __floats2half2_rn(acc[mt][nt][0], acc[mt][nt][1]);
            if (row0 + 8 < M_NODES)
                *(__half2*)(C + (size_t)(row0 + 8) * N_HID + col) =
                    __floats2half2_rn(acc[mt][nt][2], acc[mt][nt][3]);
        }
    }
}

// ---------------------------------------------------------------------------
// Binning kernels. count/permute: 4 edges per thread for atomic-latency ILP.
// ---------------------------------------------------------------------------
__global__ __launch_bounds__(256) void count_kernel(
    const int* __restrict__ edge_index)
{
    int q = blockIdx.x * blockDim.x + threadIdx.x;
    int e = q * 4;
    if (e >= NUM_EDGES) return;
    int4 d = *(const int4*)(edge_index + NUM_EDGES + e);
    atomicAdd(&g_deg[d.x], 1);
    atomicAdd(&g_deg[d.y], 1);
    atomicAdd(&g_deg[d.z], 1);
    atomicAdd(&g_deg[d.w], 1);
}

__global__ __launch_bounds__(256) void scan1_kernel()
{
    __shared__ int sh[256];
    int i = blockIdx.x * 256 + threadIdx.x;
    int v = (i < M_NODES) ? g_deg[i] : 0;
    sh[threadIdx.x] = v;
    __syncthreads();
    #pragma unroll
    for (int off = 1; off < 256; off <<= 1) {
        int t = (threadIdx.x >= off) ? sh[threadIdx.x - off] : 0;
        __syncthreads();
        sh[threadIdx.x] += t;
        __syncthreads();
    }
    if (i < M_NODES) g_start[i] = sh[threadIdx.x] - v;
    if (threadIdx.x == 255) g_bsum[blockIdx.x] = sh[255];
}

__global__ __launch_bounds__(256) void scan2_kernel()
{
    __shared__ int sh[256];
    int v = (threadIdx.x < SCAN_NB) ? g_bsum[threadIdx.x] : 0;
    sh[threadIdx.x] = v;
    __syncthreads();
    #pragma unroll
    for (int off = 1; off < 256; off <<= 1) {
        int t = (threadIdx.x >= off) ? sh[threadIdx.x - off] : 0;
        __syncthreads();
        sh[threadIdx.x] += t;
        __syncthreads();
    }
    if (threadIdx.x < SCAN_NB) g_bsum[threadIdx.x] = sh[threadIdx.x] - v;
}

__global__ __launch_bounds__(256) void scan3_kernel()
{
    int i = blockIdx.x * 256 + threadIdx.x;
    if (i >= M_NODES) return;
    int s = g_start[i] + g_bsum[blockIdx.x];
    g_start[i]  = s;
    g_cursor[i] = s;
}

__global__ __launch_bounds__(256) void permute_kernel(
    const int* __restrict__ edge_index,
    const float* __restrict__ edge_weight)
{
    int q = blockIdx.x * blockDim.x + threadIdx.x;
    int e = q * 4;
    if (e >= NUM_EDGES) return;

    int4   s = *(const int4*)  (edge_index + e);
    int4   d = *(const int4*)  (edge_index + NUM_EDGES + e);
    float4 w = *(const float4*)(edge_weight + e);

    int p0 = atomicAdd(&g_cursor[d.x], 1);
    int p1 = atomicAdd(&g_cursor[d.y], 1);
    int p2 = atomicAdd(&g_cursor[d.z], 1);
    int p3 = atomicAdd(&g_cursor[d.w], 1);

    g_edge[p0] = make_int2(s.x, __float_as_int(w.x));
    g_edge[p1] = make_int2(s.y, __float_as_int(w.y));
    g_edge[p2] = make_int2(s.z, __float_as_int(w.z));
    g_edge[p3] = make_int2(s.w, __float_as_int(w.w));
}

// ---------------------------------------------------------------------------
// Aggregate + bias + relu + log_softmax, fused. One warp per dst row.
// Gather loop unrolled 4x: 4 independent uint2 loads in flight (MLP=4).
// FMA order per accumulator identical to the serial version.
// ---------------------------------------------------------------------------
__global__ __launch_bounds__(256) void aggregate_kernel(
    const __half* __restrict__ support,
    const float* __restrict__ bias,
    float* __restrict__ out)
{
    int row  = blockIdx.x * 8 + (threadIdx.x >> 5);
    int lane = threadIdx.x & 31;
    if (row >= M_NODES) return;

    int start = g_start[row];
    int deg   = g_deg[row];
    int end   = start + deg;

    float4 acc = make_float4(0.f, 0.f, 0.f, 0.f);

    for (int base = start; base < end; base += 32) {
        int n = end - base;
        if (n > 32) n = 32;
        int   s = 0;
        float w = 0.f;
        if (lane < n) {
            int2 r = __ldg(g_edge + base + lane);
            s = r.x;
            w = __int_as_float(r.y);
        }

        int k = 0;
        #pragma unroll 1
        for (; k + 4 <= n; k += 4) {
            int   s0 = __shfl_sync(0xFFFFFFFF, s, k    );
            int   s1 = __shfl_sync(0xFFFFFFFF, s, k + 1);
            int   s2 = __shfl_sync(0xFFFFFFFF, s, k + 2);
            int   s3 = __shfl_sync(0xFFFFFFFF, s, k + 3);
            float w0 = __shfl_sync(0xFFFFFFFF, w, k    );
            float w1 = __shfl_sync(0xFFFFFFFF, w, k + 1);
            float w2 = __shfl_sync(0xFFFFFFFF, w, k + 2);
            float w3 = __shfl_sync(0xFFFFFFFF, w, k + 3);

            uint2 r0 = __ldg((const uint2*)(support + (size_t)s0 * N_HID) + lane);
            uint2 r1 = __ldg((const uint2*)(support + (size_t)s1 * N_HID) + lane);
            uint2 r2 = __ldg((const uint2*)(support + (size_t)s2 * N_HID) + lane);
            uint2 r3 = __ldg((const uint2*)(support + (size_t)s3 * N_HID) + lane);

            {
                float2 f0 = __half22float2(*(__half2*)&r0.x);
                float2 f1 = __half22float2(*(__half2*)&r0.y);
                acc.x = fmaf(f0.x, w0, acc.x);
                acc.y = fmaf(f0.y, w0, acc.y);
                acc.z = fmaf(f1.x, w0, acc.z);
                acc.w = fmaf(f1.y, w0, acc.w);
            }
            {
                float2 f0 = __half22float2(*(__half2*)&r1.x);
                float2 f1 = __half22float2(*(__half2*)&r1.y);
                acc.x = fmaf(f0.x, w1, acc.x);
                acc.y = fmaf(f0.y, w1, acc.y);
                acc.z = fmaf(f1.x, w1, acc.z);
                acc.w = fmaf(f1.y, w1, acc.w);
            }
            {
                float2 f0 = __half22float2(*(__half2*)&r2.x);
                float2 f1 = __half22float2(*(__half2*)&r2.y);
                acc.x = fmaf(f0.x, w2, acc.x);
                acc.y = fmaf(f0.y, w2, acc.y);
                acc.z = fmaf(f1.x, w2, acc.z);
                acc.w = fmaf(f1.y, w2, acc.w);
            }
            {
                float2 f0 = __half22float2(*(__half2*)&r3.x);
                float2 f1 = __half22float2(*(__half2*)&r3.y);
                acc.x = fmaf(f0.x, w3, acc.x);
                acc.y = fmaf(f0.y, w3, acc.y);
                acc.z = fmaf(f1.x, w3, acc.z);
                acc.w = fmaf(f1.y, w3, acc.w);
            }
        }
        for (; k < n; k++) {
            int   sk = __shfl_sync(0xFFFFFFFF, s, k);
            float wk = __shfl_sync(0xFFFFFFFF, w, k);
            uint2 raw = __ldg((const uint2*)(support + (size_t)sk * N_HID) + lane);
            float2 f0 = __half22float2(*(__half2*)&raw.x);
            float2 f1 = __half22float2(*(__half2*)&raw.y);
            acc.x = fmaf(f0.x, wk, acc.x);
            acc.y = fmaf(f0.y, wk, acc.y);
            acc.z = fmaf(f1.x, wk, acc.z);
            acc.w = fmaf(f1.y, wk, acc.w);
        }
    }

    float4 b = *(const float4*)(bias + lane * 4);
    acc.x = fmaxf(acc.x + b.x, 0.f);
    acc.y = fmaxf(acc.y + b.y, 0.f);
    acc.z = fmaxf(acc.z + b.z, 0.f);
    acc.w = fmaxf(acc.w + b.w, 0.f);

    float m = fmaxf(fmaxf(acc.x, acc.y), fmaxf(acc.z, acc.w));
    #pragma unroll
    for (int off = 16; off > 0; off >>= 1)
        m = fmaxf(m, __shfl_xor_sync(0xFFFFFFFF, m, off));

    float ssum = __expf(acc.x - m) + __expf(acc.y - m) +
                 __expf(acc.z - m) + __expf(acc.w - m);
    #pragma unroll
    for (int off = 16; off > 0; off >>= 1)
        ssum += __shfl_xor_sync(0xFFFFFFFF, ssum, off);

    float lse = m + __logf(ssum);
    float4 r = make_float4(acc.x - lse, acc.y - lse, acc.z - lse, acc.w - lse);
    *(float4*)(out + (size_t)row * N_HID + lane * 4) = r;
}

// ---------------------------------------------------------------------------
// Launch: GEMM on capture stream overlapped with binning on a forked stream.
// ---------------------------------------------------------------------------
extern "C" void kernel_launch(void* const* d_in, const int* in_sizes, int n_in,
                              void* d_out, int out_size)
{
    const float* x      = (const float*)d_in[0];
    const float* weight = (const float*)d_in[1];
    const float* bias   = (const float*)d_in[2];
    const int*   eidx   = (const int*)  d_in[3];
    const float* ew     = (const float*)d_in[4];
    float* out = (float*)d_out;

    __half* support;
    cudaGetSymbolAddress((void**)&support, g_support);
    void* degp;
    cudaGetSymbolAddress(&degp, g_deg);

    const int EQB = (NUM_EDGES / 4 + 255) / 256;

    cudaStream_t s2 = 0;
    bool dual = (cudaStreamCreateWithFlags(&s2, cudaStreamNonBlocking) == cudaSuccess);

    if (dual) {
        cudaEvent_t evFork, evJoin;
        cudaEventCreateWithFlags(&evFork, cudaEventDisableTiming);
        cudaEventCreateWithFlags(&evJoin, cudaEventDisableTiming);

        cudaEventRecord(evFork, 0);
        cudaStreamWaitEvent(s2, evFork, 0);

        cudaMemsetAsync(degp, 0, M_NODES * sizeof(int), s2);
        count_kernel<<<EQB, 256, 0, s2>>>(eidx);
        scan1_kernel<<<SCAN_NB, 256, 0, s2>>>();
        scan2_kernel<<<1, 256, 0, s2>>>();
        scan3_kernel<<<SCAN_NB, 256, 0, s2>>>();
        permute_kernel<<<EQB, 256, 0, s2>>>(eidx, ew);
        cudaEventRecord(evJoin, s2);

        gemm_tf32_kernel<<<(M_NODES + 127) / 128, 256>>>(x, weight, support);

        cudaStreamWaitEvent(0, evJoin, 0);
        aggregate_kernel<<<(M_NODES + 7) / 8, 256>>>(support, bias, out);
    } else {
        gemm_tf32_kernel<<<(M_NODES + 127) / 128, 256>>>(x, weight, support);
        cudaMemsetAsync(degp, 0, M_NODES * sizeof(int));
        count_kernel<<<EQB, 256>>>(eidx);
        scan1_kernel<<<SCAN_NB, 256>>>();
        scan2_kernel<<<1, 256>>>();
        scan3_kernel<<<SCAN_NB, 256>>>();
        permute_kernel<<<EQB, 256>>>(eidx, ew);
        aggregate_kernel<<<(M_NODES + 7) / 8, 256>>>(support, bias, out);
    }
}

// round 13
// speedup vs baseline: 1.0514x; 1.0320x over previous
#include <cuda_runtime.h>
#include <cuda_fp16.h>
#include <cstdint>

#define M_NODES 50000
#define K_FEAT  256
#define N_HID   128
#define NUM_EDGES 1600000
#define SCAN_NB  ((M_NODES + 255) / 256)   // 196

// ---------------------------------------------------------------------------
// Device scratch (static; no runtime allocation)
// ---------------------------------------------------------------------------
__device__ __half g_support[M_NODES * N_HID];  // 12.8 MB (fp16)
__device__ int   g_deg[M_NODES];
__device__ int   g_start[M_NODES];
__device__ int   g_cursor[M_NODES];
__device__ int   g_bsum[SCAN_NB];
__device__ int2  g_edge[NUM_EDGES];            // (src, bitcast(w))

// ---------------------------------------------------------------------------
// Kernel A: support = x @ W  via tf32 mma.sync (m16n8k8)
// cp.async double-buffered; cvt.rna.tf32 applied at fragment read
// (numerically identical to the synchronous cvt-at-store version)
// ---------------------------------------------------------------------------
#define A_STRIDE 36
#define B_STRIDE 136
#define ABUF (128 * A_STRIDE)   // 4608 floats
#define BBUF (32 * B_STRIDE)    // 4352 floats
#define GEMM_SMEM ((2 * (ABUF + BBUF)) * 4)   // 71680 bytes

__device__ __forceinline__ uint32_t f32_to_tf32(float f) {
    uint32_t r;
    asm("cvt.rna.tf32.f32 %0, %1;" : "=r"(r) : "f"(f));
    return r;
}
__device__ __forceinline__ uint32_t bits_to_tf32(uint32_t u) {
    return f32_to_tf32(__uint_as_float(u));
}

__global__ __launch_bounds__(256) void gemm_tf32_kernel(
    const float* __restrict__ A,
    const float* __restrict__ B,
    __half* __restrict__ C)
{
    extern __shared__ float smem[];
    float* As = smem;                 // [2][ABUF]
    float* Bs = smem + 2 * ABUF;      // [2][BBUF]

    const int tid  = threadIdx.x;
    const int warp = tid >> 5;
    const int lane = tid & 31;
    const int warpM = warp >> 1;
    const int warpN = warp & 1;
    const int rbase = warpM * 32;
    const int nbase = warpN * 64;
    const int m0 = blockIdx.x * 128;

    const int qrow = lane >> 2;
    const int qcol = lane & 3;

    float acc[2][8][4];
    #pragma unroll
    for (int mt = 0; mt < 2; mt++)
        #pragma unroll
        for (int nt = 0; nt < 8; nt++)
            #pragma unroll
            for (int i = 0; i < 4; i++)
                acc[mt][nt][i] = 0.f;

    auto load_tile = [&](int buf, int k0g) {
        #pragma unroll
        for (int i = 0; i < 4; i++) {
            int f = tid + i * 256;
            int row = f >> 3;           // 0..127
            int c4  = (f & 7) * 4;      // 0..28
            int gm = m0 + row;
            uint32_t dst = (uint32_t)__cvta_generic_to_shared(
                &As[buf * ABUF + row * A_STRIDE + c4]);
            const float* src = A + (size_t)gm * K_FEAT + k0g + c4;
            int sz = (gm < M_NODES) ? 16 : 0;   // zero-fill OOB rows
            asm volatile("cp.async.cg.shared.global [%0], [%1], 16, %2;"
                         :: "r"(dst), "l"(src), "r"(sz));
        }
        #pragma unroll
        for (int i = 0; i < 4; i++) {
            int f = tid + i * 256;
            int row = f >> 5;           // 0..31
            int c4  = (f & 31) * 4;     // 0..124
            uint32_t dst = (uint32_t)__cvta_generic_to_shared(
                &Bs[buf * BBUF + row * B_STRIDE + c4]);
            const float* src = B + (size_t)(k0g + row) * N_HID + c4;
            asm volatile("cp.async.cg.shared.global [%0], [%1], 16;"
                         :: "r"(dst), "l"(src));
        }
        asm volatile("cp.async.commit_group;");
    };

    load_tile(0, 0);

    const int NT = K_FEAT / 32;   // 8 k-tiles
    for (int t = 0; t < NT; t++) {
        int buf = t & 1;
        if (t + 1 < NT) {
            load_tile(buf ^ 1, (t + 1) * 32);
            asm volatile("cp.async.wait_group 1;");
        } else {
            asm volatile("cp.async.wait_group 0;");
        }
        __syncthreads();

        const uint32_t* Ab = (const uint32_t*)&As[buf * ABUF];
        const uint32_t* Bb = (const uint32_t*)&Bs[buf * BBUF];

        #pragma unroll
        for (int ks = 0; ks < 4; ks++) {
            const int k0 = ks * 8;
            uint32_t a[2][4];
            #pragma unroll
            for (int mt = 0; mt < 2; mt++) {
                int r = rbase + mt * 16 + qrow;
                a[mt][0] = bits_to_tf32(Ab[(r    ) * A_STRIDE + k0 + qcol    ]);
                a[mt][1] = bits_to_tf32(Ab[(r + 8) * A_STRIDE + k0 + qcol    ]);
                a[mt][2] = bits_to_tf32(Ab[(r    ) * A_STRIDE + k0 + qcol + 4]);
                a[mt][3] = bits_to_tf32(Ab[(r + 8) * A_STRIDE + k0 + qcol + 4]);
            }
            uint32_t b[8][2];
            #pragma unroll
            for (int nt = 0; nt < 8; nt++) {
                int c = nbase + nt * 8 + qrow;
                b[nt][0] = bits_to_tf32(Bb[(k0 + qcol    ) * B_STRIDE + c]);
                b[nt][1] = bits_to_tf32(Bb[(k0 + qcol + 4) * B_STRIDE + c]);
            }
            #pragma unroll
            for (int mt = 0; mt < 2; mt++)
                #pragma unroll
                for (int nt = 0; nt < 8; nt++)
                    asm volatile(
                        "mma.sync.aligned.m16n8k8.row.col.f32.tf32.tf32.f32 "
                        "{%0,%1,%2,%3}, {%4,%5,%6,%7}, {%8,%9}, {%0,%1,%2,%3};"
                        : "+f"(acc[mt][nt][0]), "+f"(acc[mt][nt][1]),
                          "+f"(acc[mt][nt][2]), "+f"(acc[mt][nt][3])
                        : "r"(a[mt][0]), "r"(a[mt][1]), "r"(a[mt][2]), "r"(a[mt][3]),
                          "r"(b[nt][0]), "r"(b[nt][1]));
        }
        __syncthreads();
    }

    #pragma unroll
    for (int mt = 0; mt < 2; mt++) {
        int row0 = m0 + rbase + mt * 16 + qrow;
        #pragma unroll
        for (int nt = 0; nt < 8; nt++) {
            int col = nbase + nt * 8 + 2 * qcol;
            if (row0 < M_NODES)
                *(__half2*)(C + (size_t)row0 * N_HID + col) =
                    __floats2half2_rn(acc[mt][nt][0], acc[mt][nt][1]);
            if (row0 + 8 < M_NODES)
                *(__half2*)(C + (size_t)(row0 + 8) * N_HID + col) =
                    __floats2half2_rn(acc[mt][nt][2], acc[mt][nt][3]);
        }
    }
}

// ---------------------------------------------------------------------------
// Binning kernels (byte-identical to the 120.5us build)
// ---------------------------------------------------------------------------
__global__ __launch_bounds__(256) void count_kernel(
    const int* __restrict__ edge_index)
{
    int q = blockIdx.x * blockDim.x + threadIdx.x;
    int e = q * 4;
    if (e >= NUM_EDGES) return;
    int4 d = *(const int4*)(edge_index + NUM_EDGES + e);
    atomicAdd(&g_deg[d.x], 1);
    atomicAdd(&g_deg[d.y], 1);
    atomicAdd(&g_deg[d.z], 1);
    atomicAdd(&g_deg[d.w], 1);
}

__global__ __launch_bounds__(256) void scan1_kernel()
{
    __shared__ int sh[256];
    int i = blockIdx.x * 256 + threadIdx.x;
    int v = (i < M_NODES) ? g_deg[i] : 0;
    sh[threadIdx.x] = v;
    __syncthreads();
    #pragma unroll
    for (int off = 1; off < 256; off <<= 1) {
        int t = (threadIdx.x >= off) ? sh[threadIdx.x - off] : 0;
        __syncthreads();
        sh[threadIdx.x] += t;
        __syncthreads();
    }
    if (i < M_NODES) g_start[i] = sh[threadIdx.x] - v;
    if (threadIdx.x == 255) g_bsum[blockIdx.x] = sh[255];
}

__global__ __launch_bounds__(256) void scan2_kernel()
{
    __shared__ int sh[256];
    int v = (threadIdx.x < SCAN_NB) ? g_bsum[threadIdx.x] : 0;
    sh[threadIdx.x] = v;
    __syncthreads();
    #pragma unroll
    for (int off = 1; off < 256; off <<= 1) {
        int t = (threadIdx.x >= off) ? sh[threadIdx.x - off] : 0;
        __syncthreads();
        sh[threadIdx.x] += t;
        __syncthreads();
    }
    if (threadIdx.x < SCAN_NB) g_bsum[threadIdx.x] = sh[threadIdx.x] - v;
}

__global__ __launch_bounds__(256) void scan3_kernel()
{
    int i = blockIdx.x * 256 + threadIdx.x;
    if (i >= M_NODES) return;
    int s = g_start[i] + g_bsum[blockIdx.x];
    g_start[i]  = s;
    g_cursor[i] = s;
}

__global__ __launch_bounds__(256) void permute_kernel(
    const int* __restrict__ edge_index,
    const float* __restrict__ edge_weight)
{
    int q = blockIdx.x * blockDim.x + threadIdx.x;
    int e = q * 4;
    if (e >= NUM_EDGES) return;

    int4   s = *(const int4*)  (edge_index + e);
    int4   d = *(const int4*)  (edge_index + NUM_EDGES + e);
    float4 w = *(const float4*)(edge_weight + e);

    int p0 = atomicAdd(&g_cursor[d.x], 1);
    int p1 = atomicAdd(&g_cursor[d.y], 1);
    int p2 = atomicAdd(&g_cursor[d.z], 1);
    int p3 = atomicAdd(&g_cursor[d.w], 1);

    g_edge[p0] = make_int2(s.x, __float_as_int(w.x));
    g_edge[p1] = make_int2(s.y, __float_as_int(w.y));
    g_edge[p2] = make_int2(s.z, __float_as_int(w.z));
    g_edge[p3] = make_int2(s.w, __float_as_int(w.w));
}

// ---------------------------------------------------------------------------
// Aggregate + bias + relu + log_softmax, fused. One warp per dst row.
// (byte-identical to the 120.5us build's logic)
// ---------------------------------------------------------------------------
__global__ __launch_bounds__(256) void aggregate_kernel(
    const __half* __restrict__ support,
    const float* __restrict__ bias,
    float* __restrict__ out)
{
    int row  = blockIdx.x * 8 + (threadIdx.x >> 5);
    int lane = threadIdx.x & 31;
    if (row >= M_NODES) return;

    int start = g_start[row];
    int deg   = g_deg[row];
    int end   = start + deg;

    float4 acc = make_float4(0.f, 0.f, 0.f, 0.f);

    for (int base = start; base < end; base += 32) {
        int n = end - base;
        if (n > 32) n = 32;
        int   s = 0;
        float w = 0.f;
        if (lane < n) {
            int2 r = __ldg(g_edge + base + lane);
            s = r.x;
            w = __int_as_float(r.y);
        }
        for (int k = 0; k < n; k++) {
            int   sk = __shfl_sync(0xFFFFFFFF, s, k);
            float wk = __shfl_sync(0xFFFFFFFF, w, k);
            uint2 raw = __ldg((const uint2*)(support + (size_t)sk * N_HID) + lane);
            float2 f0 = __half22float2(*(__half2*)&raw.x);
            float2 f1 = __half22float2(*(__half2*)&raw.y);
            acc.x = fmaf(f0.x, wk, acc.x);
            acc.y = fmaf(f0.y, wk, acc.y);
            acc.z = fmaf(f1.x, wk, acc.z);
            acc.w = fmaf(f1.y, wk, acc.w);
        }
    }

    float4 b = *(const float4*)(bias + lane * 4);
    acc.x = fmaxf(acc.x + b.x, 0.f);
    acc.y = fmaxf(acc.y + b.y, 0.f);
    acc.z = fmaxf(acc.z + b.z, 0.f);
    acc.w = fmaxf(acc.w + b.w, 0.f);

    float m = fmaxf(fmaxf(acc.x, acc.y), fmaxf(acc.z, acc.w));
    #pragma unroll
    for (int off = 16; off > 0; off >>= 1)
        m = fmaxf(m, __shfl_xor_sync(0xFFFFFFFF, m, off));

    float ssum = __expf(acc.x - m) + __expf(acc.y - m) +
                 __expf(acc.z - m) + __expf(acc.w - m);
    #pragma unroll
    for (int off = 16; off > 0; off >>= 1)
        ssum += __shfl_xor_sync(0xFFFFFFFF, ssum, off);

    float lse = m + __logf(ssum);
    float4 r = make_float4(acc.x - lse, acc.y - lse, acc.z - lse, acc.w - lse);
    *(float4*)(out + (size_t)row * N_HID + lane * 4) = r;
}

// ---------------------------------------------------------------------------
// Launch: GEMM on capture stream overlapped with binning on a forked stream.
// ---------------------------------------------------------------------------
extern "C" void kernel_launch(void* const* d_in, const int* in_sizes, int n_in,
                              void* d_out, int out_size)
{
    const float* x      = (const float*)d_in[0];
    const float* weight = (const float*)d_in[1];
    const float* bias   = (const float*)d_in[2];
    const int*   eidx   = (const int*)  d_in[3];
    const float* ew     = (const float*)d_in[4];
    float* out = (float*)d_out;

    __half* support;
    cudaGetSymbolAddress((void**)&support, g_support);
    void* degp;
    cudaGetSymbolAddress(&degp, g_deg);

    cudaFuncSetAttribute(gemm_tf32_kernel,
                         cudaFuncAttributeMaxDynamicSharedMemorySize, GEMM_SMEM);

    const int EQB = (NUM_EDGES / 4 + 255) / 256;

    cudaStream_t s2 = 0;
    bool dual = (cudaStreamCreateWithFlags(&s2, cudaStreamNonBlocking) == cudaSuccess);

    if (dual) {
        cudaEvent_t evFork, evJoin;
        cudaEventCreateWithFlags(&evFork, cudaEventDisableTiming);
        cudaEventCreateWithFlags(&evJoin, cudaEventDisableTiming);

        cudaEventRecord(evFork, 0);
        cudaStreamWaitEvent(s2, evFork, 0);

        cudaMemsetAsync(degp, 0, M_NODES * sizeof(int), s2);
        count_kernel<<<EQB, 256, 0, s2>>>(eidx);
        scan1_kernel<<<SCAN_NB, 256, 0, s2>>>();
        scan2_kernel<<<1, 256, 0, s2>>>();
        scan3_kernel<<<SCAN_NB, 256, 0, s2>>>();
        permute_kernel<<<EQB, 256, 0, s2>>>(eidx, ew);
        cudaEventRecord(evJoin, s2);

        gemm_tf32_kernel<<<(M_NODES + 127) / 128, 256, GEMM_SMEM>>>(x, weight, support);

        cudaStreamWaitEvent(0, evJoin, 0);
        aggregate_kernel<<<(M_NODES + 7) / 8, 256>>>(support, bias, out);
    } else {
        gemm_tf32_kernel<<<(M_NODES + 127) / 128, 256, GEMM_SMEM>>>(x, weight, support);
        cudaMemsetAsync(degp, 0, M_NODES * sizeof(int));
        count_kernel<<<EQB, 256>>>(eidx);
        scan1_kernel<<<SCAN_NB, 256>>>();
        scan2_kernel<<<1, 256>>>();
        scan3_kernel<<<SCAN_NB, 256>>>();
        permute_kernel<<<EQB, 256>>>(eidx, ew);
        aggregate_kernel<<<(M_NODES + 7) / 8, 256>>>(support, bias, out);
    }
}